// round 1
// baseline (speedup 1.0000x reference)
#include <cuda_runtime.h>
#include <cuda_bf16.h>

// Problem constants (fixed by the reference)
#define M 4096      // nodes per layer
#define LYRS 32     // internal layers
#define K 64        // in-degree
#define NBLK 128    // persistent blocks (<= 148 SMs, all co-resident)
#define NTHR 256    // threads per block
#define NODES_PER_BLK (M / NBLK)      // 32
#define THR_PER_NODE  (NTHR / NODES_PER_BLK)  // 8
#define K_PER_THR     (K / THR_PER_NODE)      // 8

// Scratch: double-buffered node values (16 KB each) + grid barrier state.
__device__ float g_v[2][M];
__device__ unsigned int g_bar_count = 0;
__device__ volatile unsigned int g_bar_gen = 0;

// Manual grid-wide barrier. All NBLK blocks are co-resident (1 block/SM),
// so spinning is safe. Pattern: syncthreads -> elected thread fences +
// atomically arrives -> last arrival resets count and bumps generation ->
// spinners observe generation, fence, syncthreads. Cumulativity of the
// scoped fence (writes of co-block threads happen-before via bar.sync)
// makes all prior global writes visible grid-wide.
__device__ __forceinline__ void grid_barrier() {
    __syncthreads();
    if (threadIdx.x == 0) {
        __threadfence();                       // release all block's writes
        unsigned int gen = g_bar_gen;
        unsigned int old = atomicAdd(&g_bar_count, 1u);
        if (old == NBLK - 1) {
            atomicExch(&g_bar_count, 0u);      // reset for next barrier
            __threadfence();
            g_bar_gen = gen + 1;               // release
        } else {
            while (g_bar_gen == gen) { }       // spin on L2 (volatile)
        }
        __threadfence();                       // acquire side
    }
    __syncthreads();
}

__global__ void __launch_bounds__(NTHR, 1)
net_kernel(const float* __restrict__ x,
           const float* __restrict__ w_in,
           const float* __restrict__ b_in,
           const float* __restrict__ w,
           const float* __restrict__ b,
           const int*   __restrict__ igraf,
           float* __restrict__ out)
{
    __shared__ float s_v[M];                   // 16 KB staged value vector

    const int tid  = threadIdx.x;
    const int bid  = blockIdx.x;
    const int gtid = bid * NTHR + tid;

    // ---- input layer: v0 = relu(w_in * x + b_in), 4096 scalars ----
    if (gtid < M) {
        float v0 = fmaf(w_in[gtid], x[gtid], b_in[gtid]);
        g_v[0][gtid] = fmaxf(v0, 0.0f);
    }
    grid_barrier();

    const int node_local   = tid / THR_PER_NODE;    // 0..31
    const int lane_in_node = tid % THR_PER_NODE;    // 0..7
    const int node         = bid * NODES_PER_BLK + node_local;

    int cur = 0;
    for (int l = 0; l < LYRS; ++l) {
        // Stage v[cur] (16 KB) into shared memory, coalesced float4 copy.
        {
            const float4* src = reinterpret_cast<const float4*>(g_v[cur]);
            float4* dst = reinterpret_cast<float4*>(s_v);
            #pragma unroll
            for (int i = tid; i < M / 4; i += NTHR) dst[i] = src[i];
        }
        __syncthreads();

        // Each 8-thread group computes one node's K=64 dot product.
        // Lane j handles k in [8j, 8j+8): two float4 / int4 loads,
        // fully coalesced (contiguous 256 B per node, 8 KB per warp-row).
        const size_t base = ((size_t)l * M + node) * K + lane_in_node * K_PER_THR;
        const float4* wp = reinterpret_cast<const float4*>(w + base);
        const int4*   gp = reinterpret_cast<const int4*>(igraf + base);
        float4 w0 = wp[0], w1 = wp[1];
        int4   g0 = gp[0], g1 = gp[1];

        float acc;
        acc  = w0.x * s_v[g0.x];
        acc  = fmaf(w0.y, s_v[g0.y], acc);
        acc  = fmaf(w0.z, s_v[g0.z], acc);
        acc  = fmaf(w0.w, s_v[g0.w], acc);
        acc  = fmaf(w1.x, s_v[g1.x], acc);
        acc  = fmaf(w1.y, s_v[g1.y], acc);
        acc  = fmaf(w1.z, s_v[g1.z], acc);
        acc  = fmaf(w1.w, s_v[g1.w], acc);

        // Reduce across the 8-lane subgroup (stays inside the warp).
        acc += __shfl_xor_sync(0xffffffffu, acc, 1);
        acc += __shfl_xor_sync(0xffffffffu, acc, 2);
        acc += __shfl_xor_sync(0xffffffffu, acc, 4);

        if (lane_in_node == 0) {
            float z = acc + b[l * M + node];
            g_v[cur ^ 1][node] = 1.0f / (1.0f + __expf(-z));
        }
        cur ^= 1;
        grid_barrier();   // also protects s_v overwrite next iteration
    }

    // Only node M-1 of the final layer is the output.
    if (bid == 0 && tid == 0) {
        out[0] = g_v[cur][M - 1];
    }
}

extern "C" void kernel_launch(void* const* d_in, const int* in_sizes, int n_in,
                              void* d_out, int out_size) {
    const float* x     = (const float*)d_in[0];   // [M,1]
    const float* w_in  = (const float*)d_in[1];   // [M,1]
    const float* b_in  = (const float*)d_in[2];   // [M]
    const float* w     = (const float*)d_in[3];   // [L,M,K]
    const float* b     = (const float*)d_in[4];   // [L,M]
    const int*   igraf = (const int*)d_in[5];     // [L,M,K]
    float* out = (float*)d_out;

    net_kernel<<<NBLK, NTHR>>>(x, w_in, b_in, w, b, igraf, out);
}

// round 2
// speedup vs baseline: 1.4969x; 1.4969x over previous
#include <cuda_runtime.h>
#include <cuda_bf16.h>

#define M 4096
#define LYRS 32
#define K 64
#define NBLK 128
#define NTHR 512
#define NODES_PER_BLK (M / NBLK)             // 32
#define THR_PER_NODE  (NTHR / NODES_PER_BLK) // 16
#define K_PER_THR     (K / THR_PER_NODE)     // 4

// Double-buffered node values + barrier state (persist across replays;
// barrier uses entry-relative generation targets so no reset is needed).
__device__ float g_v[2][M];
__device__ unsigned int g_count = 0;
__device__ unsigned int g_gen = 0;

// Grid barrier with scoped acquire/release — no threadfence, no L1 flush.
// All NBLK blocks are co-resident (1 block/SM), spinning is safe.
__device__ __forceinline__ void grid_barrier(unsigned target) {
    __syncthreads();
    if (threadIdx.x == 0) {
        unsigned old;
        asm volatile("atom.add.release.gpu.u32 %0, [%1], %2;"
                     : "=r"(old) : "l"(&g_count), "r"(1u) : "memory");
        if (old == NBLK - 1) {
            // reset count (relaxed), then publish generation (release)
            asm volatile("st.relaxed.gpu.u32 [%0], %1;"
                         :: "l"(&g_count), "r"(0u) : "memory");
            asm volatile("st.release.gpu.u32 [%0], %1;"
                         :: "l"(&g_gen), "r"(target) : "memory");
        } else {
            unsigned g;
            do {
                asm volatile("ld.acquire.gpu.u32 %0, [%1];"
                             : "=r"(g) : "l"(&g_gen) : "memory");
            } while ((int)(g - target) < 0);
        }
    }
    __syncthreads();
}

__global__ void __launch_bounds__(NTHR, 1)
net_kernel(const float* __restrict__ x,
           const float* __restrict__ w_in,
           const float* __restrict__ b_in,
           const float* __restrict__ w,
           const float* __restrict__ b,
           const int*   __restrict__ igraf,
           float* __restrict__ out)
{
    __shared__ float s_v[M];   // 16 KB staged value vector

    const int tid = threadIdx.x;
    const int bid = blockIdx.x;

    // Entry-relative barrier base. Safe: no block can write g_gen (barrier 1
    // release) until ALL blocks have arrived, and every block reads base
    // before its first arrival.
    unsigned base_gen = *(volatile unsigned*)&g_gen;

    // ---- input layer: v0 = relu(w_in*x + b_in) ----
    const int gtid = bid * NTHR + tid;
    if (gtid < M) {
        float v0 = fmaf(w_in[gtid], x[gtid], b_in[gtid]);
        __stcg(&g_v[0][gtid], fmaxf(v0, 0.0f));
    }

    const int node_local = tid >> 4;        // /THR_PER_NODE
    const int lane       = tid & 15;
    const int node       = bid * NODES_PER_BLK + node_local;

    const size_t koff = (size_t)node * K + (size_t)lane * K_PER_THR;
    const float4* wp = reinterpret_cast<const float4*>(w + koff);
    const int4*   gp = reinterpret_cast<const int4*>(igraf + koff);
    const size_t  lstride4 = (size_t)M * K / 4;   // float4/int4 per layer

    // Prefetch layer 0 operands BEFORE the barrier (overlaps DRAM/L2 latency
    // with barrier wait).
    float4 wr = __ldg(wp);
    int4   gr = __ldg(gp);
    float  br = __ldg(b + node);

    grid_barrier(base_gen + 1);

    int cur = 0;
    #pragma unroll 1
    for (int l = 0; l < LYRS; ++l) {
        // Stage v[cur] into shared memory (coalesced .cg float4, 2 per thread).
        {
            const float4* src = reinterpret_cast<const float4*>(g_v[cur]);
            float4* dst = reinterpret_cast<float4*>(s_v);
            #pragma unroll
            for (int i = 0; i < (M / 4) / NTHR; ++i)
                dst[tid + i * NTHR] = __ldcg(src + tid + i * NTHR);
        }
        __syncthreads();

        // 4 gathered MACs per thread from shared memory.
        float acc;
        acc = wr.x * s_v[gr.x];
        acc = fmaf(wr.y, s_v[gr.y], acc);
        acc = fmaf(wr.z, s_v[gr.z], acc);
        acc = fmaf(wr.w, s_v[gr.w], acc);
        float bcur = br;

        // Prefetch NEXT layer's operands now — their latency overlaps the
        // reduction, the value write, and the entire barrier wait.
        if (l + 1 < LYRS) {
            wr = __ldg(wp + (size_t)(l + 1) * lstride4);
            gr = __ldg(gp + (size_t)(l + 1) * lstride4);
            br = __ldg(b + (size_t)(l + 1) * M + node);
        }

        // Reduce across the 16-lane node subgroup (in-warp).
        acc += __shfl_xor_sync(0xffffffffu, acc, 1);
        acc += __shfl_xor_sync(0xffffffffu, acc, 2);
        acc += __shfl_xor_sync(0xffffffffu, acc, 4);
        acc += __shfl_xor_sync(0xffffffffu, acc, 8);

        if (lane == 0) {
            float val = 1.0f / (1.0f + __expf(-(acc + bcur)));
            if (l == LYRS - 1) {
                if (node == M - 1) out[0] = val;   // final output, no barrier
            } else {
                __stcg(&g_v[cur ^ 1][node], val);
            }
        }
        cur ^= 1;
        if (l + 1 < LYRS) grid_barrier(base_gen + 2 + (unsigned)l);
    }
}

extern "C" void kernel_launch(void* const* d_in, const int* in_sizes, int n_in,
                              void* d_out, int out_size) {
    const float* x     = (const float*)d_in[0];
    const float* w_in  = (const float*)d_in[1];
    const float* b_in  = (const float*)d_in[2];
    const float* w     = (const float*)d_in[3];
    const float* b     = (const float*)d_in[4];
    const int*   igraf = (const int*)d_in[5];
    float* out = (float*)d_out;

    net_kernel<<<NBLK, NTHR>>>(x, w_in, b_in, w, b, igraf, out);
}